// round 13
// baseline (speedup 1.0000x reference)
#include <cuda_runtime.h>
#include <cstdint>
#include <cstddef>

// Problem constants
#define NNODES 50000
#define NRELS  47
#define EMB    1600
#define WS     16
#define NCLS   50
#define NCPAD  52             // padded classes so 4-col groups are 16B aligned
#define NBASES 40
#define W1COLS (NRELS * WS)   // 752
#define NPAD   768            // padded N (752 -> 768, zero pad)
#define MBLKS  391            // ceil(50000/128)

// Scratch (device globals; no allocation allowed)
__device__ int   g_cnt[NRELS * NNODES];                   // 9.4 MB
__device__ float g_W1p[(size_t)NPAD * EMB];               // 4.9 MB  fragment-order tf32
__device__ float g_Af[(size_t)MBLKS * 200 * 1024];        // 320 MB  fragment-order tf32 A
__device__ float g_H[(size_t)NNODES * NPAD];              // 153.6 MB [M][NPAD]
__device__ float g_h1[NNODES * WS];                       // 3.2 MB
__device__ float g_w2[NRELS * WS * NCLS];                 // 150.4 KB
__device__ float g_out2[(size_t)NNODES * NCPAD];          // 10.4 MB padded output accum

// ---------------------------------------------------------------------------
// helpers
// ---------------------------------------------------------------------------
__device__ __forceinline__ void red_add_v4(float* p, float a, float b, float c, float d) {
    asm volatile("red.global.add.v4.f32 [%0], {%1,%2,%3,%4};"
                 :: "l"(p), "f"(a), "f"(b), "f"(c), "f"(d) : "memory");
}
__device__ __forceinline__ unsigned f2tf(float f) {
    unsigned r;
    asm("cvt.rna.tf32.f32 %0, %1;" : "=r"(r) : "f"(f));
    return r;
}
__device__ __forceinline__ uint32_t smem_u32(const void* p) {
    uint32_t a;
    asm("{ .reg .u64 t; cvta.to.shared.u64 t, %1; cvt.u32.u64 %0, t; }" : "=r"(a) : "l"(p));
    return a;
}
__device__ __forceinline__ void mma_tf32(float* c, const unsigned* a, unsigned b0, unsigned b1) {
    asm volatile(
        "mma.sync.aligned.m16n8k8.row.col.f32.tf32.tf32.f32 "
        "{%0,%1,%2,%3}, {%4,%5,%6,%7}, {%8,%9}, {%0,%1,%2,%3};"
        : "+f"(c[0]), "+f"(c[1]), "+f"(c[2]), "+f"(c[3])
        : "r"(a[0]), "r"(a[1]), "r"(a[2]), "r"(a[3]), "r"(b0), "r"(b1));
}
#define CP_ASYNC16(sm, gp) \
    asm volatile("cp.async.cg.shared.global [%0], [%1], 16;" :: "r"(sm), "l"(gp) : "memory")
#define CP_COMMIT() asm volatile("cp.async.commit_group;" ::: "memory")
#define CP_WAIT(n)  asm volatile("cp.async.wait_group %0;" :: "n"(n) : "memory")

// ---------------------------------------------------------------------------
// zero / init
// ---------------------------------------------------------------------------
#define ZTOT (NNODES * NCPAD)
__global__ void zero_scratch_k() {
    int i = blockIdx.x * blockDim.x + threadIdx.x;
    if (i < NRELS * NNODES) g_cnt[i] = 0;
    if (i < NNODES * WS)    g_h1[i]  = 0.0f;
    if (i < ZTOT)           g_out2[i] = 0.0f;
}

// ---------------------------------------------------------------------------
// per-column degree count
// ---------------------------------------------------------------------------
__global__ void count_k(const int* __restrict__ cols, int E) {
    int i = blockIdx.x * blockDim.x + threadIdx.x;
    if (i < E) atomicAdd(&g_cnt[cols[i]], 1);
}

// ---------------------------------------------------------------------------
// A conversion: emb (row-major fp32) -> g_Af (fragment-order tf32).
// ---------------------------------------------------------------------------
#define AF_U4 (MBLKS * 200 * 8 * 32)    // 20,019,200 uint4

__global__ void cvtA_k(const float* __restrict__ A) {
    unsigned idx = blockIdx.x * blockDim.x + threadIdx.x;
    if (idx >= AF_U4) return;
    int l  = idx & 31;
    int i  = (idx >> 5) & 7;
    int sg = (idx >> 8) % 200;
    int mb = idx / (200 * 256);
    int row = mb * 128 + i * 16 + (l >> 2);
    int k   = sg * 8 + (l & 3);
    bool ok0 = row < NNODES;
    bool ok1 = (row + 8) < NNODES;
    const float* p0 = A + (size_t)row * EMB + k;
    const float* p1 = A + (size_t)(row + 8) * EMB + k;
    uint4 v;
    v.x = ok0 ? f2tf(p0[0]) : 0u;
    v.y = ok1 ? f2tf(p1[0]) : 0u;
    v.z = ok0 ? f2tf(p0[4]) : 0u;
    v.w = ok1 ? f2tf(p1[4]) : 0u;
    ((uint4*)g_Af)[idx] = v;
}

// ---------------------------------------------------------------------------
// weight packing (fragment-order tf32 for W1)
// ---------------------------------------------------------------------------
__global__ void pack_w1_k(const float* __restrict__ comps1, const float* __restrict__ bases1) {
    int idx = blockIdx.x * blockDim.x + threadIdx.x;
    if (idx >= NPAD * EMB) return;
    int slot = idx & 3;
    int lane = (idx >> 2) & 31;
    int jp   = (idx >> 7) & 15;
    int sg   = (idx >> 11) % 200;
    int nb   = idx / 409600;
    int j = jp * 2 + (slot >> 1);
    int n = nb * 256 + j * 8 + (lane >> 2);
    int k = sg * 8 + ((slot & 1) << 2) + (lane & 3);
    if (n >= W1COLS) { g_W1p[idx] = 0.0f; return; }
    int r = n / WS;
    int o = n - r * WS;
    float s = 0.0f;
    #pragma unroll 8
    for (int b = 0; b < NBASES; b++)
        s += comps1[r * NBASES + b] * bases1[((size_t)b * EMB + k) * WS + o];
    g_W1p[idx] = __uint_as_float(f2tf(s));
}

__global__ void pack_w2_k(const float* __restrict__ comps2, const float* __restrict__ bases2) {
    int idx = blockIdx.x * blockDim.x + threadIdx.x;
    if (idx >= NRELS * WS * NCLS) return;
    int r   = idx / (WS * NCLS);
    int rem = idx - r * (WS * NCLS);
    int k   = rem / NCLS;
    int c   = rem - k * NCLS;
    float s = 0.0f;
    #pragma unroll 8
    for (int b = 0; b < NBASES; b++)
        s += comps2[r * NBASES + b] * bases2[(b * WS + k) * NCLS + c];
    g_w2[idx] = s;
}

// ---------------------------------------------------------------------------
// TF32 tensor-core GEMM (mma.sync), fragment-order operands via cp.async.
// Register double-buffered fragments: load s+1's 8 uint4 while issuing s's
// 32 MMAs, hiding the LDS latency behind tensor work.
// ---------------------------------------------------------------------------
#define STG_A_BYTES 16384
#define STG_B_BYTES 32768
#define STG_BYTES   (STG_A_BYTES + STG_B_BYTES)
#define STG_FLOATS  (STG_BYTES / 4)
#define GEMM_SMEM   (4 * STG_BYTES)
#define NKT 50

__global__ void __launch_bounds__(256, 1)
gemm_tc_k(int M) {
    extern __shared__ float smemf[];
    const uint32_t sbase = smem_u32(smemf);
    const int tid  = threadIdx.x;
    const int lane = tid & 31;
    const int warp = tid >> 5;
    const int wm = warp >> 2;
    const int wn = warp & 3;
    const int nb = blockIdx.x;
    const int mb = blockIdx.y;
    const int m0 = mb * 128;
    const int n0 = nb * 256;

    const float* Abase = g_Af  + (size_t)mb * 204800;
    const float* Bbase = g_W1p + (size_t)nb * 409600;

    float acc[4][8][4];
    #pragma unroll
    for (int i = 0; i < 4; i++)
        #pragma unroll
        for (int j = 0; j < 8; j++)
            #pragma unroll
            for (int q = 0; q < 4; q++) acc[i][j][q] = 0.0f;

    auto issue = [&](int kt, int slot) {
        const uint32_t sa = sbase + slot * STG_BYTES;
        const float* ga = Abase + (size_t)kt * 4096;
        #pragma unroll
        for (int q = 0; q < 4; q++)
            CP_ASYNC16(sa + tid * 16 + q * 4096, ga + tid * 4 + q * 1024);
        const uint32_t sb = sa + STG_A_BYTES;
        const float* gb = Bbase + (size_t)kt * 8192;
        #pragma unroll
        for (int q = 0; q < 8; q++)
            CP_ASYNC16(sb + tid * 16 + q * 4096, gb + tid * 4 + q * 1024);
    };

    // prologue: 3 stages in flight
    #pragma unroll
    for (int p = 0; p < 3; p++) { issue(p, p); CP_COMMIT(); }

    uint4 afr[2][4], bfr[2][4];

    for (int kt = 0; kt < NKT; ++kt) {
        CP_WAIT(2);
        __syncthreads();
        if (kt + 3 < NKT) issue(kt + 3, (kt + 3) & 3);
        CP_COMMIT();

        const float* ps = smemf + (kt & 3) * STG_FLOATS;
        const float* pa = ps;
        const float* pb = ps + 4096;

        // prefetch fragments for s=0
        #pragma unroll
        for (int im = 0; im < 4; im++)
            afr[0][im] = *(const uint4*)(pa + ((wm * 4 + im) * 32 + lane) * 4);
        #pragma unroll
        for (int jj = 0; jj < 4; jj++)
            bfr[0][jj] = *(const uint4*)(pb + ((wn * 4 + jj) * 32 + lane) * 4);

        #pragma unroll
        for (int s = 0; s < 4; s++) {
            const int cb = s & 1;        // current frag buffer
            const int nbuf = cb ^ 1;     // next frag buffer
            if (s < 3) {
                #pragma unroll
                for (int im = 0; im < 4; im++)
                    afr[nbuf][im] = *(const uint4*)(pa + (((s + 1) * 8 + wm * 4 + im) * 32 + lane) * 4);
                #pragma unroll
                for (int jj = 0; jj < 4; jj++)
                    bfr[nbuf][jj] = *(const uint4*)(pb + (((s + 1) * 16 + wn * 4 + jj) * 32 + lane) * 4);
            }
            #pragma unroll
            for (int im = 0; im < 4; im++)
                #pragma unroll
                for (int jj = 0; jj < 4; jj++) {
                    mma_tf32(acc[im][jj * 2 + 0], (const unsigned*)&afr[cb][im], bfr[cb][jj].x, bfr[cb][jj].y);
                    mma_tf32(acc[im][jj * 2 + 1], (const unsigned*)&afr[cb][im], bfr[cb][jj].z, bfr[cb][jj].w);
                }
        }
    }

    const int rl = lane >> 2;
    const int cl2 = (lane & 3) * 2;
    #pragma unroll
    for (int im = 0; im < 4; im++) {
        int row = m0 + (wm * 4 + im) * 16 + rl;
        #pragma unroll
        for (int jn = 0; jn < 8; jn++) {
            int col = n0 + (wn * 8 + jn) * 8 + cl2;
            float* p = g_H + (size_t)row * NPAD + col;
            if (row < M)     *(float2*)p              = make_float2(acc[im][jn][0], acc[im][jn][1]);
            if (row + 8 < M) *(float2*)(p + 8 * NPAD) = make_float2(acc[im][jn][2], acc[im][jn][3]);
        }
    }
}

// ---------------------------------------------------------------------------
// SpMM layer 1
// ---------------------------------------------------------------------------
__global__ void spmm1_k(const int* __restrict__ rows, const int* __restrict__ cols, int E) {
    int e = blockIdx.x * blockDim.x + threadIdx.x;
    if (e >= E) return;
    int col = cols[e];
    int row = rows[e];
    unsigned r = (unsigned)col / NNODES;
    int n = col - (int)r * NNODES;
    float v = 1.0f / (float)g_cnt[col];
    const float4* src = (const float4*)(g_H + (size_t)n * NPAD + r * WS);
    float* dst = g_h1 + (size_t)row * WS;
    #pragma unroll
    for (int q = 0; q < 4; q++) {
        float4 x = src[q];
        red_add_v4(dst + q * 4, v * x.x, v * x.y, v * x.z, v * x.w);
    }
}

__global__ void biasrelu_k(const float* __restrict__ bias1) {
    int i = blockIdx.x * blockDim.x + threadIdx.x;
    if (i >= NNODES * WS) return;
    float x = g_h1[i] + bias1[i & (WS - 1)];
    g_h1[i] = (x > 0.0f) ? x : 0.0f;
}

// ---------------------------------------------------------------------------
// SpMM layer 2: 16 threads per edge, thread t covers classes 4t..4t+3,
// one red.add.v4 per thread into padded g_out2 (52-col rows, 16B aligned).
// ---------------------------------------------------------------------------
#define W2P_ELEMS (NRELS * WS * NCPAD)        // 39104
#define W2P_SMEM  (W2P_ELEMS * 4)             // 156416 B

__global__ void __launch_bounds__(1024)
spmm2_k(const int* __restrict__ rows, const int* __restrict__ cols, int E) {
    extern __shared__ float w2p[];
    for (int i = threadIdx.x; i < W2P_ELEMS; i += blockDim.x) {
        int r   = i / (WS * NCPAD);
        int rem = i - r * (WS * NCPAD);
        int k   = rem / NCPAD;
        int c   = rem - k * NCPAD;
        w2p[i] = (c < NCLS) ? g_w2[(r * WS + k) * NCLS + c] : 0.0f;
    }
    __syncthreads();

    const int lane = threadIdx.x & 31;
    const int sub  = lane >> 4;
    const int t    = lane & 15;
    const int gw = (blockIdx.x * blockDim.x + threadIdx.x) >> 5;
    const int nw = (gridDim.x * blockDim.x) >> 5;

    for (int eb = gw * 2; eb < E; eb += nw * 2) {
        int e = eb + sub;
        if (e >= E) continue;
        int col = cols[e];
        int row = rows[e];
        unsigned r = (unsigned)col / NNODES;
        int n = col - (int)r * NNODES;
        float v = 1.0f / (float)g_cnt[col];
        const float4* hp = (const float4*)(g_h1 + (size_t)n * WS);
        float h[16];
        *(float4*)&h[0]  = hp[0];
        *(float4*)&h[4]  = hp[1];
        *(float4*)&h[8]  = hp[2];
        *(float4*)&h[12] = hp[3];
        if (t < 13) {
            const float* w = w2p + r * (WS * NCPAD) + t * 4;
            float a0 = 0.f, a1 = 0.f, a2 = 0.f, a3 = 0.f;
            #pragma unroll
            for (int k = 0; k < 16; k++) {
                float4 wk = *(const float4*)(w + k * NCPAD);
                a0 += h[k] * wk.x;
                a1 += h[k] * wk.y;
                a2 += h[k] * wk.z;
                a3 += h[k] * wk.w;
            }
            red_add_v4(g_out2 + (size_t)row * NCPAD + t * 4, v * a0, v * a1, v * a2, v * a3);
        }
    }
}

// ---------------------------------------------------------------------------
// finalize: out = g_out2[:, :50] + bias2
// ---------------------------------------------------------------------------
__global__ void finalize_k(float* __restrict__ out, const float* __restrict__ bias2) {
    int i = blockIdx.x * blockDim.x + threadIdx.x;
    if (i >= NNODES * NCLS) return;
    int n = i / NCLS;
    int c = i - n * NCLS;
    out[i] = g_out2[(size_t)n * NCPAD + c] + bias2[c];
}

// ---------------------------------------------------------------------------
// launch
// ---------------------------------------------------------------------------
extern "C" void kernel_launch(void* const* d_in, const int* in_sizes, int n_in,
                              void* d_out, int out_size) {
    const float* emb    = (const float*)d_in[0];
    const float* comps1 = (const float*)d_in[1];
    const float* bases1 = (const float*)d_in[2];
    const float* comps2 = (const float*)d_in[3];
    const float* bases2 = (const float*)d_in[4];
    const float* bias1  = (const float*)d_in[5];
    const float* bias2  = (const float*)d_in[6];
    const int*   rows   = (const int*)d_in[7];
    const int*   cols   = (const int*)d_in[8];
    float*       out    = (float*)d_out;
    int E = in_sizes[7];

    static int attr_set = 0;
    if (!attr_set) {
        cudaFuncSetAttribute(gemm_tc_k, cudaFuncAttributeMaxDynamicSharedMemorySize, GEMM_SMEM);
        cudaFuncSetAttribute(spmm2_k, cudaFuncAttributeMaxDynamicSharedMemorySize, W2P_SMEM);
        attr_set = 1;
    }

    // order chosen so the GEMM sits at the profiler's captured launch index (3)
    cvtA_k<<<(AF_U4 + 255) / 256, 256>>>(emb);                        // 0
    pack_w1_k<<<(NPAD * EMB + 255) / 256, 256>>>(comps1, bases1);     // 1
    zero_scratch_k<<<(ZTOT + 255) / 256, 256>>>();                    // 2
    {
        dim3 grid(NPAD / 256, MBLKS);  // (3, 391)
        gemm_tc_k<<<grid, 256, GEMM_SMEM>>>(NNODES);                  // 3  <- profiled
    }
    count_k<<<(E + 255) / 256, 256>>>(cols, E);                       // 4
    pack_w2_k<<<(NRELS * WS * NCLS + 255) / 256, 256>>>(comps2, bases2); // 5
    spmm1_k<<<(E + 255) / 256, 256>>>(rows, cols, E);                 // 6
    biasrelu_k<<<(NNODES * WS + 255) / 256, 256>>>(bias1);            // 7
    spmm2_k<<<148, 1024, W2P_SMEM>>>(rows, cols, E);                  // 8
    finalize_k<<<(NNODES * NCLS + 255) / 256, 256>>>(out, bias2);     // 9
}

// round 14
// speedup vs baseline: 1.0225x; 1.0225x over previous
#include <cuda_runtime.h>
#include <cstdint>
#include <cstddef>

// Problem constants
#define NNODES 50000
#define NRELS  47
#define EMB    1600
#define WS     16
#define NCLS   50
#define NCPAD  52             // padded classes so 4-col groups are 16B aligned
#define NBASES 40
#define W1COLS (NRELS * WS)   // 752
#define NPAD   768            // padded N (752 -> 768, zero pad)
#define MBLKS  391            // ceil(50000/128)

// Scratch (device globals; no allocation allowed)
__device__ int   g_cnt[NRELS * NNODES];                   // 9.4 MB
__device__ float g_W1p[(size_t)NPAD * EMB];               // 4.9 MB  fragment-order tf32 (BN=128 blocks)
__device__ float g_Af[(size_t)MBLKS * 200 * 1024];        // 320 MB  fragment-order tf32 A
__device__ float g_H[(size_t)NNODES * NPAD];              // 153.6 MB [M][NPAD]
__device__ float g_h1[NNODES * WS];                       // 3.2 MB
__device__ float g_w2[NRELS * WS * NCLS];                 // 150.4 KB
__device__ float g_out2[(size_t)NNODES * NCPAD];          // 10.4 MB padded output accum

// ---------------------------------------------------------------------------
// helpers
// ---------------------------------------------------------------------------
__device__ __forceinline__ void red_add_v4(float* p, float a, float b, float c, float d) {
    asm volatile("red.global.add.v4.f32 [%0], {%1,%2,%3,%4};"
                 :: "l"(p), "f"(a), "f"(b), "f"(c), "f"(d) : "memory");
}
__device__ __forceinline__ unsigned f2tf(float f) {
    unsigned r;
    asm("cvt.rna.tf32.f32 %0, %1;" : "=r"(r) : "f"(f));
    return r;
}
__device__ __forceinline__ uint32_t smem_u32(const void* p) {
    uint32_t a;
    asm("{ .reg .u64 t; cvta.to.shared.u64 t, %1; cvt.u32.u64 %0, t; }" : "=r"(a) : "l"(p));
    return a;
}
__device__ __forceinline__ void mma_tf32(float* c, const unsigned* a, unsigned b0, unsigned b1) {
    asm volatile(
        "mma.sync.aligned.m16n8k8.row.col.f32.tf32.tf32.f32 "
        "{%0,%1,%2,%3}, {%4,%5,%6,%7}, {%8,%9}, {%0,%1,%2,%3};"
        : "+f"(c[0]), "+f"(c[1]), "+f"(c[2]), "+f"(c[3])
        : "r"(a[0]), "r"(a[1]), "r"(a[2]), "r"(a[3]), "r"(b0), "r"(b1));
}
#define CP_ASYNC16(sm, gp) \
    asm volatile("cp.async.cg.shared.global [%0], [%1], 16;" :: "r"(sm), "l"(gp) : "memory")
#define CP_COMMIT() asm volatile("cp.async.commit_group;" ::: "memory")
#define CP_WAIT(n)  asm volatile("cp.async.wait_group %0;" :: "n"(n) : "memory")

// ---------------------------------------------------------------------------
// zero / init
// ---------------------------------------------------------------------------
#define ZTOT (NNODES * NCPAD)
__global__ void zero_scratch_k() {
    int i = blockIdx.x * blockDim.x + threadIdx.x;
    if (i < NRELS * NNODES) g_cnt[i] = 0;
    if (i < NNODES * WS)    g_h1[i]  = 0.0f;
    if (i < ZTOT)           g_out2[i] = 0.0f;
}

// ---------------------------------------------------------------------------
// per-column degree count
// ---------------------------------------------------------------------------
__global__ void count_k(const int* __restrict__ cols, int E) {
    int i = blockIdx.x * blockDim.x + threadIdx.x;
    if (i < E) atomicAdd(&g_cnt[cols[i]], 1);
}

// ---------------------------------------------------------------------------
// A conversion: emb (row-major fp32) -> g_Af (fragment-order tf32).
// Layout (uint4): [mb][sg 0..199][i 0..7][lane], unchanged from R10.
// ---------------------------------------------------------------------------
#define AF_U4 (MBLKS * 200 * 8 * 32)    // 20,019,200 uint4

__global__ void cvtA_k(const float* __restrict__ A) {
    unsigned idx = blockIdx.x * blockDim.x + threadIdx.x;
    if (idx >= AF_U4) return;
    int l  = idx & 31;
    int i  = (idx >> 5) & 7;
    int sg = (idx >> 8) % 200;
    int mb = idx / (200 * 256);
    int row = mb * 128 + i * 16 + (l >> 2);
    int k   = sg * 8 + (l & 3);
    bool ok0 = row < NNODES;
    bool ok1 = (row + 8) < NNODES;
    const float* p0 = A + (size_t)row * EMB + k;
    const float* p1 = A + (size_t)(row + 8) * EMB + k;
    uint4 v;
    v.x = ok0 ? f2tf(p0[0]) : 0u;
    v.y = ok1 ? f2tf(p1[0]) : 0u;
    v.z = ok0 ? f2tf(p0[4]) : 0u;
    v.w = ok1 ? f2tf(p1[4]) : 0u;
    ((uint4*)g_Af)[idx] = v;
}

// ---------------------------------------------------------------------------
// weight packing (fragment-order tf32 for W1), BN=128 blocks:
// float linear = [nb 0..5][sg 0..199][jp 0..7][lane][slot]
//   j = jp*2 + (slot>>1); n = nb*128 + j*8 + (lane>>2);
//   k = sg*8 + ((slot&1)<<2) + (lane&3).
// ---------------------------------------------------------------------------
__global__ void pack_w1_k(const float* __restrict__ comps1, const float* __restrict__ bases1) {
    int idx = blockIdx.x * blockDim.x + threadIdx.x;
    if (idx >= NPAD * EMB) return;
    int slot = idx & 3;
    int lane = (idx >> 2) & 31;
    int jp   = (idx >> 7) & 7;
    int sg   = (idx >> 10) % 200;
    int nb   = idx / 204800;
    int j = jp * 2 + (slot >> 1);
    int n = nb * 128 + j * 8 + (lane >> 2);
    int k = sg * 8 + ((slot & 1) << 2) + (lane & 3);
    if (n >= W1COLS) { g_W1p[idx] = 0.0f; return; }
    int r = n / WS;
    int o = n - r * WS;
    float s = 0.0f;
    #pragma unroll 8
    for (int b = 0; b < NBASES; b++)
        s += comps1[r * NBASES + b] * bases1[((size_t)b * EMB + k) * WS + o];
    g_W1p[idx] = __uint_as_float(f2tf(s));
}

__global__ void pack_w2_k(const float* __restrict__ comps2, const float* __restrict__ bases2) {
    int idx = blockIdx.x * blockDim.x + threadIdx.x;
    if (idx >= NRELS * WS * NCLS) return;
    int r   = idx / (WS * NCLS);
    int rem = idx - r * (WS * NCLS);
    int k   = rem / NCLS;
    int c   = rem - k * NCLS;
    float s = 0.0f;
    #pragma unroll 8
    for (int b = 0; b < NBASES; b++)
        s += comps2[r * NBASES + b] * bases2[(b * WS + k) * NCLS + c];
    g_w2[idx] = s;
}

// ---------------------------------------------------------------------------
// TF32 tensor-core GEMM (mma.sync), 2 CTAs/SM.
// BM=128 BN=128 BK=32, 256 threads, warp grid 4x2, warp tile 32x64.
// 3-stage cp.async pipeline (32KB/stage), <=128 regs via launch_bounds(256,2).
// ---------------------------------------------------------------------------
#define STG_A_FLOATS 4096                    // 128x32 tf32
#define STG_B_FLOATS 4096                    // 32x128 tf32
#define STG_FLOATS   (STG_A_FLOATS + STG_B_FLOATS)
#define STG_BYTES    (STG_FLOATS * 4)        // 32768
#define GEMM_STAGES  3
#define GEMM_SMEM    (GEMM_STAGES * STG_BYTES)  // 98304
#define NKT 50

__global__ void __launch_bounds__(256, 2)
gemm_tc_k(int M) {
    extern __shared__ float smemf[];
    const uint32_t sbase = smem_u32(smemf);
    const int tid  = threadIdx.x;
    const int lane = tid & 31;
    const int warp = tid >> 5;
    const int wm = warp & 3;    // 0..3  (32 rows each)
    const int wn = warp >> 2;   // 0..1  (64 cols each)
    const int nb = blockIdx.x;  // 0..5
    const int mb = blockIdx.y;  // 0..390
    const int m0 = mb * 128;
    const int n0 = nb * 128;

    const float* Abase = g_Af  + (size_t)mb * 204800;
    const float* Bbase = g_W1p + (size_t)nb * 204800;

    float acc[2][8][4];
    #pragma unroll
    for (int i = 0; i < 2; i++)
        #pragma unroll
        for (int j = 0; j < 8; j++)
            #pragma unroll
            for (int q = 0; q < 4; q++) acc[i][j][q] = 0.0f;

    auto issue = [&](int kt, int slot) {
        const uint32_t sa = sbase + slot * STG_BYTES;
        const float* ga = Abase + (size_t)kt * STG_A_FLOATS;
        #pragma unroll
        for (int q = 0; q < 4; q++)
            CP_ASYNC16(sa + tid * 16 + q * 4096, ga + tid * 4 + q * 1024);
        const uint32_t sb = sa + STG_A_FLOATS * 4;
        const float* gb = Bbase + (size_t)kt * STG_B_FLOATS;
        #pragma unroll
        for (int q = 0; q < 4; q++)
            CP_ASYNC16(sb + tid * 16 + q * 4096, gb + tid * 4 + q * 1024);
    };

    // prologue: 3 stages in flight
    #pragma unroll
    for (int p = 0; p < GEMM_STAGES; p++) { issue(p, p); CP_COMMIT(); }

    int slot = 0;
    for (int kt = 0; kt < NKT; ++kt) {
        CP_WAIT(2);
        __syncthreads();
        const float* ps = smemf + slot * STG_FLOATS;
        const float* pa = ps;
        const float* pb = ps + STG_A_FLOATS;
        #pragma unroll
        for (int s = 0; s < 4; s++) {
            uint4 afr[2], bfr[4];
            #pragma unroll
            for (int im = 0; im < 2; im++)
                afr[im] = *(const uint4*)(pa + (s * 8 + wm * 2 + im) * 128 + lane * 4);
            #pragma unroll
            for (int jj = 0; jj < 4; jj++)
                bfr[jj] = *(const uint4*)(pb + (s * 8 + wn * 4 + jj) * 128 + lane * 4);
            #pragma unroll
            for (int im = 0; im < 2; im++)
                #pragma unroll
                for (int jj = 0; jj < 4; jj++) {
                    mma_tf32(acc[im][jj * 2 + 0], (const unsigned*)&afr[im], bfr[jj].x, bfr[jj].y);
                    mma_tf32(acc[im][jj * 2 + 1], (const unsigned*)&afr[im], bfr[jj].z, bfr[jj].w);
                }
        }
        __syncthreads();
        if (kt + GEMM_STAGES < NKT) issue(kt + GEMM_STAGES, slot);
        CP_COMMIT();
        slot = (slot + 1 == GEMM_STAGES) ? 0 : slot + 1;
    }

    // epilogue: c0=C[r][c] c1=C[r][c+1] c2=C[r+8][c] c3=C[r+8][c+1]
    const int rl = lane >> 2;
    const int cl2 = (lane & 3) * 2;
    #pragma unroll
    for (int im = 0; im < 2; im++) {
        int row = m0 + wm * 32 + im * 16 + rl;
        #pragma unroll
        for (int jn = 0; jn < 8; jn++) {
            int col = n0 + wn * 64 + jn * 8 + cl2;
            float* p = g_H + (size_t)row * NPAD + col;
            if (row < M)     *(float2*)p              = make_float2(acc[im][jn][0], acc[im][jn][1]);
            if (row + 8 < M) *(float2*)(p + 8 * NPAD) = make_float2(acc[im][jn][2], acc[im][jn][3]);
        }
    }
}

// ---------------------------------------------------------------------------
// SpMM layer 1
// ---------------------------------------------------------------------------
__global__ void spmm1_k(const int* __restrict__ rows, const int* __restrict__ cols, int E) {
    int e = blockIdx.x * blockDim.x + threadIdx.x;
    if (e >= E) return;
    int col = cols[e];
    int row = rows[e];
    unsigned r = (unsigned)col / NNODES;
    int n = col - (int)r * NNODES;
    float v = 1.0f / (float)g_cnt[col];
    const float4* src = (const float4*)(g_H + (size_t)n * NPAD + r * WS);
    float* dst = g_h1 + (size_t)row * WS;
    #pragma unroll
    for (int q = 0; q < 4; q++) {
        float4 x = src[q];
        red_add_v4(dst + q * 4, v * x.x, v * x.y, v * x.z, v * x.w);
    }
}

__global__ void biasrelu_k(const float* __restrict__ bias1) {
    int i = blockIdx.x * blockDim.x + threadIdx.x;
    if (i >= NNODES * WS) return;
    float x = g_h1[i] + bias1[i & (WS - 1)];
    g_h1[i] = (x > 0.0f) ? x : 0.0f;
}

// ---------------------------------------------------------------------------
// SpMM layer 2: 16 threads per edge, thread t covers classes 4t..4t+3,
// one red.add.v4 per thread into padded g_out2 (52-col rows, 16B aligned).
// ---------------------------------------------------------------------------
#define W2P_ELEMS (NRELS * WS * NCPAD)        // 39104
#define W2P_SMEM  (W2P_ELEMS * 4)             // 156416 B

__global__ void __launch_bounds__(1024)
spmm2_k(const int* __restrict__ rows, const int* __restrict__ cols, int E) {
    extern __shared__ float w2p[];
    for (int i = threadIdx.x; i < W2P_ELEMS; i += blockDim.x) {
        int r   = i / (WS * NCPAD);
        int rem = i - r * (WS * NCPAD);
        int k   = rem / NCPAD;
        int c   = rem - k * NCPAD;
        w2p[i] = (c < NCLS) ? g_w2[(r * WS + k) * NCLS + c] : 0.0f;
    }
    __syncthreads();

    const int lane = threadIdx.x & 31;
    const int sub  = lane >> 4;
    const int t    = lane & 15;
    const int gw = (blockIdx.x * blockDim.x + threadIdx.x) >> 5;
    const int nw = (gridDim.x * blockDim.x) >> 5;

    for (int eb = gw * 2; eb < E; eb += nw * 2) {
        int e = eb + sub;
        if (e >= E) continue;
        int col = cols[e];
        int row = rows[e];
        unsigned r = (unsigned)col / NNODES;
        int n = col - (int)r * NNODES;
        float v = 1.0f / (float)g_cnt[col];
        const float4* hp = (const float4*)(g_h1 + (size_t)n * WS);
        float h[16];
        *(float4*)&h[0]  = hp[0];
        *(float4*)&h[4]  = hp[1];
        *(float4*)&h[8]  = hp[2];
        *(float4*)&h[12] = hp[3];
        if (t < 13) {
            const float* w = w2p + r * (WS * NCPAD) + t * 4;
            float a0 = 0.f, a1 = 0.f, a2 = 0.f, a3 = 0.f;
            #pragma unroll
            for (int k = 0; k < 16; k++) {
                float4 wk = *(const float4*)(w + k * NCPAD);
                a0 += h[k] * wk.x;
                a1 += h[k] * wk.y;
                a2 += h[k] * wk.z;
                a3 += h[k] * wk.w;
            }
            red_add_v4(g_out2 + (size_t)row * NCPAD + t * 4, v * a0, v * a1, v * a2, v * a3);
        }
    }
}

// ---------------------------------------------------------------------------
// finalize: out = g_out2[:, :50] + bias2
// ---------------------------------------------------------------------------
__global__ void finalize_k(float* __restrict__ out, const float* __restrict__ bias2) {
    int i = blockIdx.x * blockDim.x + threadIdx.x;
    if (i >= NNODES * NCLS) return;
    int n = i / NCLS;
    int c = i - n * NCLS;
    out[i] = g_out2[(size_t)n * NCPAD + c] + bias2[c];
}

// ---------------------------------------------------------------------------
// launch
// ---------------------------------------------------------------------------
extern "C" void kernel_launch(void* const* d_in, const int* in_sizes, int n_in,
                              void* d_out, int out_size) {
    const float* emb    = (const float*)d_in[0];
    const float* comps1 = (const float*)d_in[1];
    const float* bases1 = (const float*)d_in[2];
    const float* comps2 = (const float*)d_in[3];
    const float* bases2 = (const float*)d_in[4];
    const float* bias1  = (const float*)d_in[5];
    const float* bias2  = (const float*)d_in[6];
    const int*   rows   = (const int*)d_in[7];
    const int*   cols   = (const int*)d_in[8];
    float*       out    = (float*)d_out;
    int E = in_sizes[7];

    static int attr_set = 0;
    if (!attr_set) {
        cudaFuncSetAttribute(gemm_tc_k, cudaFuncAttributeMaxDynamicSharedMemorySize, GEMM_SMEM);
        cudaFuncSetAttribute(spmm2_k, cudaFuncAttributeMaxDynamicSharedMemorySize, W2P_SMEM);
        attr_set = 1;
    }

    // order chosen so the GEMM sits at the profiler's captured launch index (3)
    cvtA_k<<<(AF_U4 + 255) / 256, 256>>>(emb);                        // 0
    pack_w1_k<<<(NPAD * EMB + 255) / 256, 256>>>(comps1, bases1);     // 1
    zero_scratch_k<<<(ZTOT + 255) / 256, 256>>>();                    // 2
    {
        dim3 grid(NPAD / 128, MBLKS);  // (6, 391)
        gemm_tc_k<<<grid, 256, GEMM_SMEM>>>(NNODES);                  // 3  <- profiled
    }
    count_k<<<(E + 255) / 256, 256>>>(cols, E);                       // 4
    pack_w2_k<<<(NRELS * WS * NCLS + 255) / 256, 256>>>(comps2, bases2); // 5
    spmm1_k<<<(E + 255) / 256, 256>>>(rows, cols, E);                 // 6
    biasrelu_k<<<(NNODES * WS + 255) / 256, 256>>>(bias1);            // 7
    spmm2_k<<<148, 1024, W2P_SMEM>>>(rows, cols, E);                  // 8
    finalize_k<<<(NNODES * NCLS + 255) / 256, 256>>>(out, bias2);     // 9
}

// round 17
// speedup vs baseline: 1.0339x; 1.0111x over previous
#include <cuda_runtime.h>
#include <cstdint>
#include <cstddef>

// Problem constants
#define NNODES 50000
#define NRELS  47
#define EMB    1600
#define WS     16
#define NCLS   50
#define NCPAD  52             // padded classes so 4-col groups are 16B aligned
#define NBASES 40
#define W1COLS (NRELS * WS)   // 752
#define NPAD   768            // padded N (752 -> 768, zero pad)
#define MBLKS  391            // ceil(50000/128)

// Scratch (device globals; no allocation allowed)
__device__ int   g_cnt[NRELS * NNODES];                   // 9.4 MB
__device__ float g_W1p[(size_t)NPAD * EMB];               // 4.9 MB  fragment-order tf32 (BN=128 blocks)
__device__ float g_Af[(size_t)MBLKS * 200 * 1024];        // 320 MB  fragment-order tf32 A
__device__ float g_H[(size_t)NNODES * NPAD];              // 153.6 MB [M][NPAD]
__device__ float g_h1[NNODES * WS];                       // 3.2 MB
__device__ float g_w2[NRELS * WS * NCLS];                 // 150.4 KB
__device__ float g_out2[(size_t)NNODES * NCPAD];          // 10.4 MB padded output accum

// ---------------------------------------------------------------------------
// helpers
// ---------------------------------------------------------------------------
__device__ __forceinline__ void red_add_v4(float* p, float a, float b, float c, float d) {
    asm volatile("red.global.add.v4.f32 [%0], {%1,%2,%3,%4};"
                 :: "l"(p), "f"(a), "f"(b), "f"(c), "f"(d) : "memory");
}
__device__ __forceinline__ unsigned f2tf(float f) {
    unsigned r;
    asm("cvt.rna.tf32.f32 %0, %1;" : "=r"(r) : "f"(f));
    return r;
}
__device__ __forceinline__ uint32_t smem_u32(const void* p) {
    uint32_t a;
    asm("{ .reg .u64 t; cvta.to.shared.u64 t, %1; cvt.u32.u64 %0, t; }" : "=r"(a) : "l"(p));
    return a;
}
__device__ __forceinline__ void mma_tf32(float* c, const unsigned* a, unsigned b0, unsigned b1) {
    asm volatile(
        "mma.sync.aligned.m16n8k8.row.col.f32.tf32.tf32.f32 "
        "{%0,%1,%2,%3}, {%4,%5,%6,%7}, {%8,%9}, {%0,%1,%2,%3};"
        : "+f"(c[0]), "+f"(c[1]), "+f"(c[2]), "+f"(c[3])
        : "r"(a[0]), "r"(a[1]), "r"(a[2]), "r"(a[3]), "r"(b0), "r"(b1));
}
#define CP_ASYNC16(sm, gp) \
    asm volatile("cp.async.cg.shared.global [%0], [%1], 16;" :: "r"(sm), "l"(gp) : "memory")
#define CP_COMMIT() asm volatile("cp.async.commit_group;" ::: "memory")
#define CP_WAIT(n)  asm volatile("cp.async.wait_group %0;" :: "n"(n) : "memory")

// ---------------------------------------------------------------------------
// zero / init
// ---------------------------------------------------------------------------
#define ZTOT (NNODES * NCPAD)
__global__ void zero_scratch_k() {
    int i = blockIdx.x * blockDim.x + threadIdx.x;
    if (i < NRELS * NNODES) g_cnt[i] = 0;
    if (i < NNODES * WS)    g_h1[i]  = 0.0f;
    if (i < ZTOT)           g_out2[i] = 0.0f;
}

// ---------------------------------------------------------------------------
// per-column degree count
// ---------------------------------------------------------------------------
__global__ void count_k(const int* __restrict__ cols, int E) {
    int i = blockIdx.x * blockDim.x + threadIdx.x;
    if (i < E) atomicAdd(&g_cnt[cols[i]], 1);
}

// ---------------------------------------------------------------------------
// A conversion: emb (row-major fp32) -> g_Af (fragment-order tf32).
// ---------------------------------------------------------------------------
#define AF_U4 (MBLKS * 200 * 8 * 32)    // 20,019,200 uint4

__global__ void cvtA_k(const float* __restrict__ A) {
    unsigned idx = blockIdx.x * blockDim.x + threadIdx.x;
    if (idx >= AF_U4) return;
    int l  = idx & 31;
    int i  = (idx >> 5) & 7;
    int sg = (idx >> 8) % 200;
    int mb = idx / (200 * 256);
    int row = mb * 128 + i * 16 + (l >> 2);
    int k   = sg * 8 + (l & 3);
    bool ok0 = row < NNODES;
    bool ok1 = (row + 8) < NNODES;
    const float* p0 = A + (size_t)row * EMB + k;
    const float* p1 = A + (size_t)(row + 8) * EMB + k;
    uint4 v;
    v.x = ok0 ? f2tf(p0[0]) : 0u;
    v.y = ok1 ? f2tf(p1[0]) : 0u;
    v.z = ok0 ? f2tf(p0[4]) : 0u;
    v.w = ok1 ? f2tf(p1[4]) : 0u;
    ((uint4*)g_Af)[idx] = v;
}

// ---------------------------------------------------------------------------
// weight packing (fragment-order tf32 for W1), BN=128 blocks
// ---------------------------------------------------------------------------
__global__ void pack_w1_k(const float* __restrict__ comps1, const float* __restrict__ bases1) {
    int idx = blockIdx.x * blockDim.x + threadIdx.x;
    if (idx >= NPAD * EMB) return;
    int slot = idx & 3;
    int lane = (idx >> 2) & 31;
    int jp   = (idx >> 7) & 7;
    int sg   = (idx >> 10) % 200;
    int nb   = idx / 204800;
    int j = jp * 2 + (slot >> 1);
    int n = nb * 128 + j * 8 + (lane >> 2);
    int k = sg * 8 + ((slot & 1) << 2) + (lane & 3);
    if (n >= W1COLS) { g_W1p[idx] = 0.0f; return; }
    int r = n / WS;
    int o = n - r * WS;
    float s = 0.0f;
    #pragma unroll 8
    for (int b = 0; b < NBASES; b++)
        s += comps1[r * NBASES + b] * bases1[((size_t)b * EMB + k) * WS + o];
    g_W1p[idx] = __uint_as_float(f2tf(s));
}

__global__ void pack_w2_k(const float* __restrict__ comps2, const float* __restrict__ bases2) {
    int idx = blockIdx.x * blockDim.x + threadIdx.x;
    if (idx >= NRELS * WS * NCLS) return;
    int r   = idx / (WS * NCLS);
    int rem = idx - r * (WS * NCLS);
    int k   = rem / NCLS;
    int c   = rem - k * NCLS;
    float s = 0.0f;
    #pragma unroll 8
    for (int b = 0; b < NBASES; b++)
        s += comps2[r * NBASES + b] * bases2[(b * WS + k) * NCLS + c];
    g_w2[idx] = s;
}

// ---------------------------------------------------------------------------
// TF32 tensor-core GEMM (mma.sync), 2 CTAs/SM.
// BM=128 BN=128 BK=32, 256 threads, warp grid 4x2, warp tile 32x64.
// ---------------------------------------------------------------------------
#define STG_A_FLOATS 4096
#define STG_B_FLOATS 4096
#define STG_FLOATS   (STG_A_FLOATS + STG_B_FLOATS)
#define STG_BYTES    (STG_FLOATS * 4)        // 32768
#define GEMM_STAGES  3
#define GEMM_SMEM    (GEMM_STAGES * STG_BYTES)  // 98304
#define NKT 50

__global__ void __launch_bounds__(256, 2)
gemm_tc_k(int M) {
    extern __shared__ float smemf[];
    const uint32_t sbase = smem_u32(smemf);
    const int tid  = threadIdx.x;
    const int lane = tid & 31;
    const int warp = tid >> 5;
    const int wm = warp & 3;
    const int wn = warp >> 2;
    const int nb = blockIdx.x;
    const int mb = blockIdx.y;
    const int m0 = mb * 128;
    const int n0 = nb * 128;

    const float* Abase = g_Af  + (size_t)mb * 204800;
    const float* Bbase = g_W1p + (size_t)nb * 204800;

    float acc[2][8][4];
    #pragma unroll
    for (int i = 0; i < 2; i++)
        #pragma unroll
        for (int j = 0; j < 8; j++)
            #pragma unroll
            for (int q = 0; q < 4; q++) acc[i][j][q] = 0.0f;

    auto issue = [&](int kt, int slot) {
        const uint32_t sa = sbase + slot * STG_BYTES;
        const float* ga = Abase + (size_t)kt * STG_A_FLOATS;
        #pragma unroll
        for (int q = 0; q < 4; q++)
            CP_ASYNC16(sa + tid * 16 + q * 4096, ga + tid * 4 + q * 1024);
        const uint32_t sb = sa + STG_A_FLOATS * 4;
        const float* gb = Bbase + (size_t)kt * STG_B_FLOATS;
        #pragma unroll
        for (int q = 0; q < 4; q++)
            CP_ASYNC16(sb + tid * 16 + q * 4096, gb + tid * 4 + q * 1024);
    };

    #pragma unroll
    for (int p = 0; p < GEMM_STAGES; p++) { issue(p, p); CP_COMMIT(); }

    int slot = 0;
    for (int kt = 0; kt < NKT; ++kt) {
        CP_WAIT(2);
        __syncthreads();
        const float* ps = smemf + slot * STG_FLOATS;
        const float* pa = ps;
        const float* pb = ps + STG_A_FLOATS;
        #pragma unroll
        for (int s = 0; s < 4; s++) {
            uint4 afr[2], bfr[4];
            #pragma unroll
            for (int im = 0; im < 2; im++)
                afr[im] = *(const uint4*)(pa + (s * 8 + wm * 2 + im) * 128 + lane * 4);
            #pragma unroll
            for (int jj = 0; jj < 4; jj++)
                bfr[jj] = *(const uint4*)(pb + (s * 8 + wn * 4 + jj) * 128 + lane * 4);
            #pragma unroll
            for (int im = 0; im < 2; im++)
                #pragma unroll
                for (int jj = 0; jj < 4; jj++) {
                    mma_tf32(acc[im][jj * 2 + 0], (const unsigned*)&afr[im], bfr[jj].x, bfr[jj].y);
                    mma_tf32(acc[im][jj * 2 + 1], (const unsigned*)&afr[im], bfr[jj].z, bfr[jj].w);
                }
        }
        __syncthreads();
        if (kt + GEMM_STAGES < NKT) issue(kt + GEMM_STAGES, slot);
        CP_COMMIT();
        slot = (slot + 1 == GEMM_STAGES) ? 0 : slot + 1;
    }

    const int rl = lane >> 2;
    const int cl2 = (lane & 3) * 2;
    #pragma unroll
    for (int im = 0; im < 2; im++) {
        int row = m0 + wm * 32 + im * 16 + rl;
        #pragma unroll
        for (int jn = 0; jn < 8; jn++) {
            int col = n0 + wn * 64 + jn * 8 + cl2;
            float* p = g_H + (size_t)row * NPAD + col;
            if (row < M)     *(float2*)p              = make_float2(acc[im][jn][0], acc[im][jn][1]);
            if (row + 8 < M) *(float2*)(p + 8 * NPAD) = make_float2(acc[im][jn][2], acc[im][jn][3]);
        }
    }
}

// ---------------------------------------------------------------------------
// SpMM layer 1
// ---------------------------------------------------------------------------
__global__ void spmm1_k(const int* __restrict__ rows, const int* __restrict__ cols, int E) {
    int e = blockIdx.x * blockDim.x + threadIdx.x;
    if (e >= E) return;
    int col = cols[e];
    int row = rows[e];
    unsigned r = (unsigned)col / NNODES;
    int n = col - (int)r * NNODES;
    float v = 1.0f / (float)g_cnt[col];
    const float4* src = (const float4*)(g_H + (size_t)n * NPAD + r * WS);
    float* dst = g_h1 + (size_t)row * WS;
    #pragma unroll
    for (int q = 0; q < 4; q++) {
        float4 x = src[q];
        red_add_v4(dst + q * 4, v * x.x, v * x.y, v * x.z, v * x.w);
    }
}

__global__ void biasrelu_k(const float* __restrict__ bias1) {
    int i = blockIdx.x * blockDim.x + threadIdx.x;
    if (i >= NNODES * WS) return;
    float x = g_h1[i] + bias1[i & (WS - 1)];
    g_h1[i] = (x > 0.0f) ? x : 0.0f;
}

// ---------------------------------------------------------------------------
// SpMM layer 2: 16 threads per edge, thread t covers classes 4t..4t+3
// ---------------------------------------------------------------------------
#define W2P_ELEMS (NRELS * WS * NCPAD)        // 39104
#define W2P_SMEM  (W2P_ELEMS * 4)             // 156416 B

__global__ void __launch_bounds__(1024)
spmm2_k(const int* __restrict__ rows, const int* __restrict__ cols, int E) {
    extern __shared__ float w2p[];
    for (int i = threadIdx.x; i < W2P_ELEMS; i += blockDim.x) {
        int r   = i / (WS * NCPAD);
        int rem = i - r * (WS * NCPAD);
        int k   = rem / NCPAD;
        int c   = rem - k * NCPAD;
        w2p[i] = (c < NCLS) ? g_w2[(r * WS + k) * NCLS + c] : 0.0f;
    }
    __syncthreads();

    const int lane = threadIdx.x & 31;
    const int sub  = lane >> 4;
    const int t    = lane & 15;
    const int gw = (blockIdx.x * blockDim.x + threadIdx.x) >> 5;
    const int nw = (gridDim.x * blockDim.x) >> 5;

    for (int eb = gw * 2; eb < E; eb += nw * 2) {
        int e = eb + sub;
        if (e >= E) continue;
        int col = cols[e];
        int row = rows[e];
        unsigned r = (unsigned)col / NNODES;
        int n = col - (int)r * NNODES;
        float v = 1.0f / (float)g_cnt[col];
        const float4* hp = (const float4*)(g_h1 + (size_t)n * WS);
        float h[16];
        *(float4*)&h[0]  = hp[0];
        *(float4*)&h[4]  = hp[1];
        *(float4*)&h[8]  = hp[2];
        *(float4*)&h[12] = hp[3];
        if (t < 13) {
            const float* w = w2p + r * (WS * NCPAD) + t * 4;
            float a0 = 0.f, a1 = 0.f, a2 = 0.f, a3 = 0.f;
            #pragma unroll
            for (int k = 0; k < 16; k++) {
                float4 wk = *(const float4*)(w + k * NCPAD);
                a0 += h[k] * wk.x;
                a1 += h[k] * wk.y;
                a2 += h[k] * wk.z;
                a3 += h[k] * wk.w;
            }
            red_add_v4(g_out2 + (size_t)row * NCPAD + t * 4, v * a0, v * a1, v * a2, v * a3);
        }
    }
}

// ---------------------------------------------------------------------------
// finalize: out = g_out2[:, :50] + bias2
// ---------------------------------------------------------------------------
__global__ void finalize_k(float* __restrict__ out, const float* __restrict__ bias2) {
    int i = blockIdx.x * blockDim.x + threadIdx.x;
    if (i >= NNODES * NCLS) return;
    int n = i / NCLS;
    int c = i - n * NCLS;
    out[i] = g_out2[(size_t)n * NCPAD + c] + bias2[c];
}

// ---------------------------------------------------------------------------
// launch — multi-stream fork/join (capture-legal: event-based fork from the
// capture stream, side streams join back via events before dependent work).
// ---------------------------------------------------------------------------
extern "C" void kernel_launch(void* const* d_in, const int* in_sizes, int n_in,
                              void* d_out, int out_size) {
    const float* emb    = (const float*)d_in[0];
    const float* comps1 = (const float*)d_in[1];
    const float* bases1 = (const float*)d_in[2];
    const float* comps2 = (const float*)d_in[3];
    const float* bases2 = (const float*)d_in[4];
    const float* bias1  = (const float*)d_in[5];
    const float* bias2  = (const float*)d_in[6];
    const int*   rows   = (const int*)d_in[7];
    const int*   cols   = (const int*)d_in[8];
    float*       out    = (float*)d_out;
    int E = in_sizes[7];

    static int init_done = 0;
    static cudaStream_t s1, s2;
    static cudaEvent_t eRoot, e1, e2;
    if (!init_done) {
        cudaFuncSetAttribute(gemm_tc_k, cudaFuncAttributeMaxDynamicSharedMemorySize, GEMM_SMEM);
        cudaFuncSetAttribute(spmm2_k, cudaFuncAttributeMaxDynamicSharedMemorySize, W2P_SMEM);
        cudaStreamCreateWithFlags(&s1, cudaStreamNonBlocking);
        cudaStreamCreateWithFlags(&s2, cudaStreamNonBlocking);
        cudaEventCreateWithFlags(&eRoot, cudaEventDisableTiming);
        cudaEventCreateWithFlags(&e1, cudaEventDisableTiming);
        cudaEventCreateWithFlags(&e2, cudaEventDisableTiming);
        init_done = 1;
    }

    // fork from the (capturing) default stream
    cudaEventRecord(eRoot, 0);
    cudaStreamWaitEvent(s1, eRoot, 0);
    cudaStreamWaitEvent(s2, eRoot, 0);

    // stream 0: A conversion (longest prep, DRAM-bound)
    cvtA_k<<<(AF_U4 + 255) / 256, 256>>>(emb);

    // s1: W1 packing (L1/FMA-bound — overlaps cvtA)
    pack_w1_k<<<(NPAD * EMB + 255) / 256, 256, 0, s1>>>(comps1, bases1);
    cudaEventRecord(e1, s1);

    // s2: zero scratch -> degree counts -> W2 packing (overlaps cvtA + gemm)
    zero_scratch_k<<<(ZTOT + 255) / 256, 256, 0, s2>>>();
    count_k<<<(E + 255) / 256, 256, 0, s2>>>(cols, E);
    pack_w2_k<<<(NRELS * WS * NCLS + 255) / 256, 256, 0, s2>>>(comps2, bases2);
    cudaEventRecord(e2, s2);

    // join pack_w1 before the GEMM (needs g_Af + g_W1p)
    cudaStreamWaitEvent(0, e1, 0);
    {
        dim3 grid(NPAD / 128, MBLKS);  // (6, 391)
        gemm_tc_k<<<grid, 256, GEMM_SMEM>>>(NNODES);
    }

    // join s2 before sparse aggregation (needs g_cnt, zeroed g_h1/g_out2, g_w2)
    cudaStreamWaitEvent(0, e2, 0);
    spmm1_k<<<(E + 255) / 256, 256>>>(rows, cols, E);
    biasrelu_k<<<(NNODES * WS + 255) / 256, 256>>>(bias1);
    spmm2_k<<<148, 1024, W2P_SMEM>>>(rows, cols, E);
    finalize_k<<<(NNODES * NCLS + 255) / 256, 256>>>(out, bias2);
}